// round 6
// baseline (speedup 1.0000x reference)
#include <cuda_runtime.h>
#include <cstdint>

#define CS   1024
#define HD   16
#define DDIM 64
#define CZ   128
#define NI   1024
#define NJ   1024

typedef unsigned long long ull;

// ---------------- scratch (device globals: allocation-free) ----------------
__device__ float g_q[NI * CS];                  // 4 MB
__device__ float g_k[NJ * CS];                  // 4 MB
__device__ float g_v[NJ * CS];                  // 4 MB
__device__ float g_g[NI * CS];                  // 4 MB
__device__ float g_o[NI * CS];                  // 4 MB  (holds g .* o after attn)
__device__ float g_z[(size_t)HD * NI * NJ];     // 64 MB

// ---------------- packed fp32x2 helpers ----------------
static __device__ __forceinline__ ull f2pack(float x, float y) {
    ull r; asm("mov.b64 %0, {%1, %2};" : "=l"(r) : "f"(x), "f"(y)); return r;
}
static __device__ __forceinline__ ull f2dup(float x) {
    ull r; asm("mov.b64 %0, {%1, %1};" : "=l"(r) : "f"(x)); return r;
}
static __device__ __forceinline__ void ffma2(ull& d, ull a, ull b) {
    asm("fma.rn.f32x2 %0, %1, %2, %0;" : "+l"(d) : "l"(a), "l"(b));
}
static __device__ __forceinline__ float2 f2unpack(ull v) {
    float2 r; asm("mov.b64 {%0, %1}, %2;" : "=f"(r.x), "=f"(r.y) : "l"(v)); return r;
}

// =====================================================================
// 128x128x32 NT SGEMM body (f32x2): C[M,N] = A @ B^T
// MODE: 0 = plain, 1 = +biasv[col], 2 = sigmoid
// =====================================================================
template <int MODE>
__device__ __forceinline__ void gemm128_body(
    float* As, float* Bs,                          // each [32][132]
    int row0, int col0,
    const float* __restrict__ A, const float* __restrict__ B,
    const float* __restrict__ biasv, float* __restrict__ C)
{
    const int SL = 132;
    const int tid = threadIdx.x;
    const int tx = tid & 15, ty = tid >> 4;

    ull acc[8][4];
#pragma unroll
    for (int i = 0; i < 8; i++)
#pragma unroll
        for (int j = 0; j < 4; j++) acc[i][j] = 0ull;

    for (int kt = 0; kt < CS; kt += 32) {
#pragma unroll
        for (int p = 0; p < 4; p++) {
            const int idx = p * 256 + tid;     // 0..1023
            const int r   = idx >> 3;          // 0..127
            const int kc4 = (idx & 7) * 4;     // 0..28
            const float4 av = *(const float4*)&A[(size_t)(row0 + r) * CS + kt + kc4];
            As[(kc4 + 0) * SL + r] = av.x;
            As[(kc4 + 1) * SL + r] = av.y;
            As[(kc4 + 2) * SL + r] = av.z;
            As[(kc4 + 3) * SL + r] = av.w;
            const float4 bv = *(const float4*)&B[(size_t)(col0 + r) * CS + kt + kc4];
            Bs[(kc4 + 0) * SL + r] = bv.x;
            Bs[(kc4 + 1) * SL + r] = bv.y;
            Bs[(kc4 + 2) * SL + r] = bv.z;
            Bs[(kc4 + 3) * SL + r] = bv.w;
        }
        __syncthreads();
#pragma unroll 8
        for (int kk = 0; kk < 32; kk++) {
            const float4 a0 = *(const float4*)&As[kk * SL + ty * 8];
            const float4 a1 = *(const float4*)&As[kk * SL + ty * 8 + 4];
            const ulonglong2 b0 = *(const ulonglong2*)&Bs[kk * SL + tx * 8];
            const ulonglong2 b1 = *(const ulonglong2*)&Bs[kk * SL + tx * 8 + 4];
            const ull bb[4] = {b0.x, b0.y, b1.x, b1.y};
            const ull aa[8] = {f2dup(a0.x), f2dup(a0.y), f2dup(a0.z), f2dup(a0.w),
                               f2dup(a1.x), f2dup(a1.y), f2dup(a1.z), f2dup(a1.w)};
#pragma unroll
            for (int i = 0; i < 8; i++)
#pragma unroll
                for (int j = 0; j < 4; j++)
                    ffma2(acc[i][j], aa[i], bb[j]);
        }
        __syncthreads();
    }

#pragma unroll
    for (int i = 0; i < 8; i++) {
        const int row = row0 + ty * 8 + i;
#pragma unroll
        for (int jv = 0; jv < 2; jv++) {
            const int col = col0 + tx * 8 + jv * 4;
            const float2 c0 = f2unpack(acc[i][jv * 2 + 0]);
            const float2 c1 = f2unpack(acc[i][jv * 2 + 1]);
            float4 v = make_float4(c0.x, c0.y, c1.x, c1.y);
            if (MODE == 1) {
                const float4 bb = *(const float4*)&biasv[col];
                v.x += bb.x; v.y += bb.y; v.z += bb.z; v.w += bb.w;
            } else if (MODE == 2) {
                v.x = 1.f / (1.f + __expf(-v.x));
                v.y = 1.f / (1.f + __expf(-v.y));
                v.z = 1.f / (1.f + __expf(-v.z));
                v.w = 1.f / (1.f + __expf(-v.w));
            }
            *(float4*)&C[(size_t)row * CS + col] = v;
        }
    }
}

// =====================================================================
// Fused: blocks [0,256): 4 projection GEMMs. blocks [256,2304): z.
// z blocks: JT=2 j per thread (spill-free: ~80 regs vs 128-reg cap).
// z[h,i,j] = bias[i,j,:]·Wz[:,h] + (1-mask[j])*(-1e6)
// =====================================================================
__global__ __launch_bounds__(256, 2) void fused_projz_kernel(
    const float* __restrict__ s, const float* __restrict__ kin,
    const float* __restrict__ Wq, const float* __restrict__ bq,
    const float* __restrict__ Wk, const float* __restrict__ Wv,
    const float* __restrict__ Wg,
    const float* __restrict__ bias, const float* __restrict__ Wz,
    const float* __restrict__ mask)
{
    __shared__ __align__(16) float sm[2 * 32 * 132];   // 33.8 KB
    const int b = blockIdx.x;

    if (b < 256) {
        float* As = sm;
        float* Bs = sm + 32 * 132;
        const int which = b >> 6;
        const int t = b & 63;
        const int row0 = (t >> 3) * 128;
        const int col0 = (t & 7) * 128;
        switch (which) {
        case 0: gemm128_body<1>(As, Bs, row0, col0, s,   Wq, bq,      g_q); break;
        case 1: gemm128_body<0>(As, Bs, row0, col0, kin, Wk, nullptr, g_k); break;
        case 2: gemm128_body<0>(As, Bs, row0, col0, kin, Wv, nullptr, g_v); break;
        default: gemm128_body<2>(As, Bs, row0, col0, s,  Wg, nullptr, g_g); break;
        }
        return;
    }

    // ---------------- z part (JT = 2 j per thread) ----------------
    ull* Wzs = (ull*)sm;                 // Wzs[hp*128 + c] = (Wz[c][2hp], Wz[c][2hp+1])
    for (int t = threadIdx.x; t < (HD / 2) * CZ; t += 256) {
        const int hp = t >> 7, c = t & 127;
        Wzs[t] = f2pack(Wz[c * HD + hp * 2], Wz[c * HD + hp * 2 + 1]);
    }
    __syncthreads();

    const int idx = b - 256;                        // 0..2047
    const int i   = idx >> 1;
    const int jb  = (idx & 1) * 512 + threadIdx.x;  // j = jb + t*256, t in {0,1}
    const float* base = bias + (size_t)i * NJ * CZ;

    ull acc2[2][HD / 2];
#pragma unroll
    for (int t = 0; t < 2; t++)
#pragma unroll
        for (int hp = 0; hp < HD / 2; hp++) acc2[t][hp] = 0ull;

    // prefetch first bias chunk for both j
    float4 bv[2];
#pragma unroll
    for (int t = 0; t < 2; t++)
        bv[t] = *(const float4*)&base[(size_t)(jb + t * 256) * CZ];

    for (int c4 = 0; c4 < CZ; c4 += 4) {
        float4 nv[2];
        if (c4 + 4 < CZ) {
#pragma unroll
            for (int t = 0; t < 2; t++)
                nv[t] = *(const float4*)&base[(size_t)(jb + t * 256) * CZ + c4 + 4];
        }
        // pair {x,y}
        {
            ull d0[2], d1[2];
#pragma unroll
            for (int t = 0; t < 2; t++) { d0[t] = f2dup(bv[t].x); d1[t] = f2dup(bv[t].y); }
#pragma unroll
            for (int hp = 0; hp < HD / 2; hp++) {
                const ulonglong2 w = *(const ulonglong2*)&Wzs[hp * CZ + c4];
#pragma unroll
                for (int t = 0; t < 2; t++) {
                    ffma2(acc2[t][hp], d0[t], w.x);
                    ffma2(acc2[t][hp], d1[t], w.y);
                }
            }
        }
        // pair {z,w}
        {
            ull d0[2], d1[2];
#pragma unroll
            for (int t = 0; t < 2; t++) { d0[t] = f2dup(bv[t].z); d1[t] = f2dup(bv[t].w); }
#pragma unroll
            for (int hp = 0; hp < HD / 2; hp++) {
                const ulonglong2 w = *(const ulonglong2*)&Wzs[hp * CZ + c4 + 2];
#pragma unroll
                for (int t = 0; t < 2; t++) {
                    ffma2(acc2[t][hp], d0[t], w.x);
                    ffma2(acc2[t][hp], d1[t], w.y);
                }
            }
        }
#pragma unroll
        for (int t = 0; t < 2; t++) bv[t] = nv[t];
    }

#pragma unroll
    for (int t = 0; t < 2; t++) {
        const int j = jb + t * 256;
        const float mterm = (1.0f - mask[j]) * (-1000000.0f);
#pragma unroll
        for (int hp = 0; hp < HD / 2; hp++) {
            const float2 zz = f2unpack(acc2[t][hp]);
            g_z[((size_t)(2 * hp + 0) * NI + i) * NJ + j] = zz.x + mterm;
            g_z[((size_t)(2 * hp + 1) * NI + i) * NJ + j] = zz.y + mterm;
        }
    }
}

// =====================================================================
// Attention, fp32, no-max softmax (logits bounded; mask -> exp -> 0).
// block = (64-row i-tile, head). BJ = 32. f32x2 in QK and PV.
// Q staged in smem as pre-duplicated f32x2 (kills per-d dup MOVs in QK).
// Epilogue multiplies by gate g and stores g.*o.
// Dynamic smem: Qs2(32KB ull) + Ks(9.2KB) + Vs(8.7KB) + Ps(9.2KB) = 59.9KB
// =====================================================================
extern __shared__ __align__(16) ull attn_sm[];

__global__ __launch_bounds__(256) void attn_kernel()
{
    ull*   Qs2 = attn_sm;                       // [64 d][64 i] dup'd q
    float* Ks  = (float*)(attn_sm + 64 * 64);   // [64 d][36 j]
    float* Vs  = Ks + 64 * 36;                  // [32 j][68 d]
    float* Ps  = Vs + 32 * 68;                  // [64 i][36 j]

    const int tid = threadIdx.x;
    const int tx = tid & 15, ty = tid >> 4;
    const int h  = blockIdx.y;
    const int i0 = blockIdx.x * 64;

    // load Q tile (64 rows x 64 d), dup'd + transposed into Qs2[d][i]
#pragma unroll
    for (int p = 0; p < 4; p++) {
        const int idx = p * 256 + tid;
        const int r  = idx >> 4;
        const int c4 = (idx & 15) * 4;
        const float4 qv = *(const float4*)&g_q[(size_t)(i0 + r) * CS + h * DDIM + c4];
        Qs2[(c4 + 0) * 64 + r] = f2dup(qv.x);
        Qs2[(c4 + 1) * 64 + r] = f2dup(qv.y);
        Qs2[(c4 + 2) * 64 + r] = f2dup(qv.z);
        Qs2[(c4 + 3) * 64 + r] = f2dup(qv.w);
    }

    float l[4];
    ull oacc[4][2];
#pragma unroll
    for (int r = 0; r < 4; r++) {
        l[r] = 0.f;
        oacc[r][0] = 0ull; oacc[r][1] = 0ull;
    }

    for (int j0 = 0; j0 < NJ; j0 += 32) {
        __syncthreads();   // prev-iter readers done; Q ready (iter 0)
#pragma unroll
        for (int p = 0; p < 2; p++) {
            const int idx = p * 256 + tid;
            const int r  = idx >> 4;
            const int c4 = (idx & 15) * 4;
            const float4 kv = *(const float4*)&g_k[(size_t)(j0 + r) * CS + h * DDIM + c4];
            Ks[(c4 + 0) * 36 + r] = kv.x;
            Ks[(c4 + 1) * 36 + r] = kv.y;
            Ks[(c4 + 2) * 36 + r] = kv.z;
            Ks[(c4 + 3) * 36 + r] = kv.w;
            const float4 vv = *(const float4*)&g_v[(size_t)(j0 + r) * CS + h * DDIM + c4];
            *(float4*)&Vs[r * 68 + c4] = vv;
        }
        __syncthreads();

        // S = Q K^T  (4 rows x 1 packed j-pair per thread, f32x2, no dups)
        ull s2p[4];
#pragma unroll
        for (int r = 0; r < 4; r++) s2p[r] = 0ull;
#pragma unroll 8
        for (int d = 0; d < 64; d++) {
            const ulonglong2 a01 = *(const ulonglong2*)&Qs2[d * 64 + ty * 4];
            const ulonglong2 a23 = *(const ulonglong2*)&Qs2[d * 64 + ty * 4 + 2];
            const ull bp = *(const ull*)&Ks[d * 36 + tx * 2];
            ffma2(s2p[0], a01.x, bp);
            ffma2(s2p[1], a01.y, bp);
            ffma2(s2p[2], a23.x, bp);
            ffma2(s2p[3], a23.y, bp);
        }

        // p = exp(s/8 + z); accumulate per-thread row sum
#pragma unroll
        for (int r = 0; r < 4; r++) {
            const float2 sv = f2unpack(s2p[r]);
            const float2 zv = *(const float2*)
                &g_z[((size_t)h * NI + (i0 + ty * 4 + r)) * NJ + j0 + tx * 2];
            const float p0 = __expf(fmaf(sv.x, 0.125f, zv.x));
            const float p1 = __expf(fmaf(sv.y, 0.125f, zv.y));
            l[r] += p0 + p1;
            *(float2*)&Ps[(ty * 4 + r) * 36 + tx * 2] = make_float2(p0, p1);
        }
        __syncthreads();

        // O += P @ V   (f32x2 along d)
#pragma unroll
        for (int jj4 = 0; jj4 < 32; jj4 += 4) {
            ull pd[4][4];
#pragma unroll
            for (int r = 0; r < 4; r++) {
                const float4 pv = *(const float4*)&Ps[(ty * 4 + r) * 36 + jj4];
                pd[r][0] = f2dup(pv.x); pd[r][1] = f2dup(pv.y);
                pd[r][2] = f2dup(pv.z); pd[r][3] = f2dup(pv.w);
            }
#pragma unroll
            for (int q = 0; q < 4; q++) {
                const ulonglong2 v2 = *(const ulonglong2*)&Vs[(jj4 + q) * 68 + tx * 4];
#pragma unroll
                for (int r = 0; r < 4; r++) {
                    ffma2(oacc[r][0], pd[r][q], v2.x);
                    ffma2(oacc[r][1], pd[r][q], v2.y);
                }
            }
        }
    }

#pragma unroll
    for (int r = 0; r < 4; r++) {
        float ls = l[r];
#pragma unroll
        for (int off = 8; off >= 1; off >>= 1)
            ls += __shfl_xor_sync(0xffffffffu, ls, off);
        const float inv = 1.f / ls;
        const float2 o0 = f2unpack(oacc[r][0]);
        const float2 o1 = f2unpack(oacc[r][1]);
        const size_t pos = (size_t)(i0 + ty * 4 + r) * CS + h * DDIM + tx * 4;
        const float4 gv = *(const float4*)&g_g[pos];     // fuse gate here
        float4 ov = make_float4(o0.x * inv * gv.x, o0.y * inv * gv.y,
                                o1.x * inv * gv.z, o1.y * inv * gv.w);
        *(float4*)&g_o[pos] = ov;
    }
}

#define ATTN_SMEM (64 * 64 * 8 + (64 * 36 + 32 * 68 + 64 * 36) * 4)

// =====================================================================
// out = (g.*o) @ Wo^T   128x64x32 tiles, 8x2-ull microtile, f32x2
// =====================================================================
__global__ __launch_bounds__(256) void final_kernel(
    const float* __restrict__ Wo, float* __restrict__ out)
{
    __shared__ __align__(16) float As[32 * 132];
    __shared__ __align__(16) float Bs[32 * 68];
    const int SLA = 132, SLB = 68;
    const int tid = threadIdx.x;
    const int tx = tid & 15, ty = tid >> 4;
    const int row0 = blockIdx.y * 128, col0 = blockIdx.x * 64;

    ull acc[8][2];
#pragma unroll
    for (int i = 0; i < 8; i++) { acc[i][0] = 0ull; acc[i][1] = 0ull; }

    for (int kt = 0; kt < CS; kt += 32) {
#pragma unroll
        for (int p = 0; p < 4; p++) {
            const int idx = p * 256 + tid;     // 0..1023
            const int r   = idx >> 3;          // 0..127
            const int kc4 = (idx & 7) * 4;     // 0..28
            const float4 av = *(const float4*)&g_o[(size_t)(row0 + r) * CS + kt + kc4];
            As[(kc4 + 0) * SLA + r] = av.x;
            As[(kc4 + 1) * SLA + r] = av.y;
            As[(kc4 + 2) * SLA + r] = av.z;
            As[(kc4 + 3) * SLA + r] = av.w;
        }
#pragma unroll
        for (int p = 0; p < 2; p++) {
            const int idx = p * 256 + tid;     // 0..511
            const int r   = idx >> 3;          // 0..63
            const int kc4 = (idx & 7) * 4;
            const float4 bv = *(const float4*)&Wo[(size_t)(col0 + r) * CS + kt + kc4];
            Bs[(kc4 + 0) * SLB + r] = bv.x;
            Bs[(kc4 + 1) * SLB + r] = bv.y;
            Bs[(kc4 + 2) * SLB + r] = bv.z;
            Bs[(kc4 + 3) * SLB + r] = bv.w;
        }
        __syncthreads();
#pragma unroll 8
        for (int kk = 0; kk < 32; kk++) {
            const float4 a0 = *(const float4*)&As[kk * SLA + ty * 8];
            const float4 a1 = *(const float4*)&As[kk * SLA + ty * 8 + 4];
            const ulonglong2 b2 = *(const ulonglong2*)&Bs[kk * SLB + tx * 4];
            const ull aa[8] = {f2dup(a0.x), f2dup(a0.y), f2dup(a0.z), f2dup(a0.w),
                               f2dup(a1.x), f2dup(a1.y), f2dup(a1.z), f2dup(a1.w)};
#pragma unroll
            for (int i = 0; i < 8; i++) {
                ffma2(acc[i][0], aa[i], b2.x);
                ffma2(acc[i][1], aa[i], b2.y);
            }
        }
        __syncthreads();
    }

#pragma unroll
    for (int i = 0; i < 8; i++) {
        const int row = row0 + ty * 8 + i;
        const float2 c0 = f2unpack(acc[i][0]);
        const float2 c1 = f2unpack(acc[i][1]);
        float4 v = make_float4(c0.x, c0.y, c1.x, c1.y);
        *(float4*)&out[(size_t)row * CS + col0 + tx * 4] = v;
    }
}

// =====================================================================
extern "C" void kernel_launch(void* const* d_in, const int* in_sizes, int n_in,
                              void* d_out, int out_size)
{
    (void)in_sizes; (void)n_in; (void)out_size;
    const float* s    = (const float*)d_in[0];
    const float* kin  = (const float*)d_in[1];
    const float* mask = (const float*)d_in[2];
    const float* bias = (const float*)d_in[3];
    const float* Wq   = (const float*)d_in[4];
    const float* bq   = (const float*)d_in[5];
    const float* Wk   = (const float*)d_in[6];
    const float* Wv   = (const float*)d_in[7];
    const float* Wg   = (const float*)d_in[8];
    const float* Wo   = (const float*)d_in[9];
    const float* Wz   = (const float*)d_in[10];
    float* out = (float*)d_out;

    // idempotent, host-side (not a captured stream op)
    cudaFuncSetAttribute(attn_kernel,
                         cudaFuncAttributeMaxDynamicSharedMemorySize, ATTN_SMEM);

    fused_projz_kernel<<<256 + 2 * NI, 256>>>(s, kin, Wq, bq, Wk, Wv, Wg, bias, Wz, mask);
    attn_kernel<<<dim3(NI / 64, HD), 256, ATTN_SMEM>>>();
    final_kernel<<<dim3(CS / 64, CS / 128), 256>>>(Wo, out);
}

// round 7
// speedup vs baseline: 1.0064x; 1.0064x over previous
#include <cuda_runtime.h>
#include <cstdint>

#define CS   1024
#define HD   16
#define DDIM 64
#define CZ   128
#define NI   1024
#define NJ   1024

typedef unsigned long long ull;

// ---------------- scratch (device globals: allocation-free) ----------------
__device__ float g_q[NI * CS];                  // 4 MB
__device__ float g_k[NJ * CS];                  // 4 MB
__device__ float g_v[NJ * CS];                  // 4 MB
__device__ float g_g[NI * CS];                  // 4 MB
__device__ float g_o[NI * CS];                  // 4 MB  (holds g .* o after attn)
__device__ float g_z[(size_t)HD * NI * NJ];     // 64 MB

// ---------------- packed fp32x2 helpers ----------------
static __device__ __forceinline__ ull f2pack(float x, float y) {
    ull r; asm("mov.b64 %0, {%1, %2};" : "=l"(r) : "f"(x), "f"(y)); return r;
}
static __device__ __forceinline__ ull f2dup(float x) {
    ull r; asm("mov.b64 %0, {%1, %1};" : "=l"(r) : "f"(x)); return r;
}
static __device__ __forceinline__ void ffma2(ull& d, ull a, ull b) {
    asm("fma.rn.f32x2 %0, %1, %2, %0;" : "+l"(d) : "l"(a), "l"(b));
}
static __device__ __forceinline__ float2 f2unpack(ull v) {
    float2 r; asm("mov.b64 {%0, %1}, %2;" : "=f"(r.x), "=f"(r.y) : "l"(v)); return r;
}

// =====================================================================
// 128x128x32 NT SGEMM body (f32x2): C[M,N] = A @ B^T
// MODE: 0 = plain, 1 = +biasv[col], 2 = sigmoid
// =====================================================================
template <int MODE>
__device__ __forceinline__ void gemm128_body(
    float* As, float* Bs,                          // each [32][132]
    int row0, int col0,
    const float* __restrict__ A, const float* __restrict__ B,
    const float* __restrict__ biasv, float* __restrict__ C)
{
    const int SL = 132;
    const int tid = threadIdx.x;
    const int tx = tid & 15, ty = tid >> 4;

    ull acc[8][4];
#pragma unroll
    for (int i = 0; i < 8; i++)
#pragma unroll
        for (int j = 0; j < 4; j++) acc[i][j] = 0ull;

    for (int kt = 0; kt < CS; kt += 32) {
#pragma unroll
        for (int p = 0; p < 4; p++) {
            const int idx = p * 256 + tid;     // 0..1023
            const int r   = idx >> 3;          // 0..127
            const int kc4 = (idx & 7) * 4;     // 0..28
            const float4 av = *(const float4*)&A[(size_t)(row0 + r) * CS + kt + kc4];
            As[(kc4 + 0) * SL + r] = av.x;
            As[(kc4 + 1) * SL + r] = av.y;
            As[(kc4 + 2) * SL + r] = av.z;
            As[(kc4 + 3) * SL + r] = av.w;
            const float4 bv = *(const float4*)&B[(size_t)(col0 + r) * CS + kt + kc4];
            Bs[(kc4 + 0) * SL + r] = bv.x;
            Bs[(kc4 + 1) * SL + r] = bv.y;
            Bs[(kc4 + 2) * SL + r] = bv.z;
            Bs[(kc4 + 3) * SL + r] = bv.w;
        }
        __syncthreads();
#pragma unroll 8
        for (int kk = 0; kk < 32; kk++) {
            const float4 a0 = *(const float4*)&As[kk * SL + ty * 8];
            const float4 a1 = *(const float4*)&As[kk * SL + ty * 8 + 4];
            const ulonglong2 b0 = *(const ulonglong2*)&Bs[kk * SL + tx * 8];
            const ulonglong2 b1 = *(const ulonglong2*)&Bs[kk * SL + tx * 8 + 4];
            const ull bb[4] = {b0.x, b0.y, b1.x, b1.y};
            const ull aa[8] = {f2dup(a0.x), f2dup(a0.y), f2dup(a0.z), f2dup(a0.w),
                               f2dup(a1.x), f2dup(a1.y), f2dup(a1.z), f2dup(a1.w)};
#pragma unroll
            for (int i = 0; i < 8; i++)
#pragma unroll
                for (int j = 0; j < 4; j++)
                    ffma2(acc[i][j], aa[i], bb[j]);
        }
        __syncthreads();
    }

#pragma unroll
    for (int i = 0; i < 8; i++) {
        const int row = row0 + ty * 8 + i;
#pragma unroll
        for (int jv = 0; jv < 2; jv++) {
            const int col = col0 + tx * 8 + jv * 4;
            const float2 c0 = f2unpack(acc[i][jv * 2 + 0]);
            const float2 c1 = f2unpack(acc[i][jv * 2 + 1]);
            float4 v = make_float4(c0.x, c0.y, c1.x, c1.y);
            if (MODE == 1) {
                const float4 bb = *(const float4*)&biasv[col];
                v.x += bb.x; v.y += bb.y; v.z += bb.z; v.w += bb.w;
            } else if (MODE == 2) {
                v.x = 1.f / (1.f + __expf(-v.x));
                v.y = 1.f / (1.f + __expf(-v.y));
                v.z = 1.f / (1.f + __expf(-v.z));
                v.w = 1.f / (1.f + __expf(-v.w));
            }
            *(float4*)&C[(size_t)row * CS + col] = v;
        }
    }
}

// q = s@Wq^T+bq | k = kin@Wk^T | v = kin@Wv^T | g = sigmoid(s@Wg^T)
__global__ __launch_bounds__(256) void proj4_kernel(
    const float* __restrict__ s, const float* __restrict__ kin,
    const float* __restrict__ Wq, const float* __restrict__ bq,
    const float* __restrict__ Wk, const float* __restrict__ Wv,
    const float* __restrict__ Wg)
{
    __shared__ __align__(16) float sm[2 * 32 * 132];   // 33.8 KB
    float* As = sm;
    float* Bs = sm + 32 * 132;
    const int row0 = blockIdx.y * 128;
    const int col0 = blockIdx.x * 128;
    switch (blockIdx.z) {
    case 0: gemm128_body<1>(As, Bs, row0, col0, s,   Wq, bq,      g_q); break;
    case 1: gemm128_body<0>(As, Bs, row0, col0, kin, Wk, nullptr, g_k); break;
    case 2: gemm128_body<0>(As, Bs, row0, col0, kin, Wv, nullptr, g_v); break;
    default: gemm128_body<2>(As, Bs, row0, col0, s,  Wg, nullptr, g_g); break;
    }
}

// =====================================================================
// z_kernel (standalone, JT=2): own register budget -> high occupancy,
// 4 LDG.128 in flight per thread. DRAM-bound by the 512 MB bias read.
// z[h,i,j] = bias[i,j,:]·Wz[:,h] + (1-mask[j])*(-1e6)
// =====================================================================
__global__ __launch_bounds__(256) void z_kernel(
    const float* __restrict__ bias, const float* __restrict__ Wz,
    const float* __restrict__ mask)
{
    __shared__ ull Wzs[(HD / 2) * CZ];   // Wzs[hp*128+c] = (Wz[c][2hp], Wz[c][2hp+1])
    for (int t = threadIdx.x; t < (HD / 2) * CZ; t += 256) {
        const int hp = t >> 7, c = t & 127;
        Wzs[t] = f2pack(Wz[c * HD + hp * 2], Wz[c * HD + hp * 2 + 1]);
    }
    __syncthreads();

    const int idx = blockIdx.x;                     // 0..2047
    const int i   = idx >> 1;
    const int jb  = (idx & 1) * 512 + threadIdx.x;  // j = jb + t*256, t in {0,1}
    const float* base = bias + (size_t)i * NJ * CZ;

    ull acc2[2][HD / 2];
#pragma unroll
    for (int t = 0; t < 2; t++)
#pragma unroll
        for (int hp = 0; hp < HD / 2; hp++) acc2[t][hp] = 0ull;

    float4 bv[2];
#pragma unroll
    for (int t = 0; t < 2; t++)
        bv[t] = *(const float4*)&base[(size_t)(jb + t * 256) * CZ];

    for (int c4 = 0; c4 < CZ; c4 += 4) {
        float4 nv[2];
        if (c4 + 4 < CZ) {
#pragma unroll
            for (int t = 0; t < 2; t++)
                nv[t] = *(const float4*)&base[(size_t)(jb + t * 256) * CZ + c4 + 4];
        }
        {
            ull d0[2], d1[2];
#pragma unroll
            for (int t = 0; t < 2; t++) { d0[t] = f2dup(bv[t].x); d1[t] = f2dup(bv[t].y); }
#pragma unroll
            for (int hp = 0; hp < HD / 2; hp++) {
                const ulonglong2 w = *(const ulonglong2*)&Wzs[hp * CZ + c4];
#pragma unroll
                for (int t = 0; t < 2; t++) {
                    ffma2(acc2[t][hp], d0[t], w.x);
                    ffma2(acc2[t][hp], d1[t], w.y);
                }
            }
        }
        {
            ull d0[2], d1[2];
#pragma unroll
            for (int t = 0; t < 2; t++) { d0[t] = f2dup(bv[t].z); d1[t] = f2dup(bv[t].w); }
#pragma unroll
            for (int hp = 0; hp < HD / 2; hp++) {
                const ulonglong2 w = *(const ulonglong2*)&Wzs[hp * CZ + c4 + 2];
#pragma unroll
                for (int t = 0; t < 2; t++) {
                    ffma2(acc2[t][hp], d0[t], w.x);
                    ffma2(acc2[t][hp], d1[t], w.y);
                }
            }
        }
#pragma unroll
        for (int t = 0; t < 2; t++) bv[t] = nv[t];
    }

#pragma unroll
    for (int t = 0; t < 2; t++) {
        const int j = jb + t * 256;
        const float mterm = (1.0f - mask[j]) * (-1000000.0f);
#pragma unroll
        for (int hp = 0; hp < HD / 2; hp++) {
            const float2 zz = f2unpack(acc2[t][hp]);
            g_z[((size_t)(2 * hp + 0) * NI + i) * NJ + j] = zz.x + mterm;
            g_z[((size_t)(2 * hp + 1) * NI + i) * NJ + j] = zz.y + mterm;
        }
    }
}

// =====================================================================
// Attention, fp32, no-max softmax (logits bounded; mask -> exp -> 0).
// block = (64-row i-tile, head). BJ = 32. f32x2 in QK and PV.
// Epilogue multiplies by gate g and stores g.*o.   (R5-measured version)
// =====================================================================
__global__ __launch_bounds__(256) void attn_kernel()
{
    __shared__ __align__(16) float Qs[64 * 68];   // [d][i]
    __shared__ __align__(16) float Ks[64 * 36];   // [d][j]
    __shared__ __align__(16) float Vs[32 * 68];   // [j][d]
    __shared__ __align__(16) float Ps[64 * 36];   // [i][j]

    const int tid = threadIdx.x;
    const int tx = tid & 15, ty = tid >> 4;
    const int h  = blockIdx.y;
    const int i0 = blockIdx.x * 64;

    // load Q tile (64 rows x 64 d), transposed into Qs[d][i]
#pragma unroll
    for (int p = 0; p < 4; p++) {
        const int idx = p * 256 + tid;
        const int r  = idx >> 4;
        const int c4 = (idx & 15) * 4;
        const float4 qv = *(const float4*)&g_q[(size_t)(i0 + r) * CS + h * DDIM + c4];
        Qs[(c4 + 0) * 68 + r] = qv.x;
        Qs[(c4 + 1) * 68 + r] = qv.y;
        Qs[(c4 + 2) * 68 + r] = qv.z;
        Qs[(c4 + 3) * 68 + r] = qv.w;
    }

    float l[4];
    ull oacc[4][2];
#pragma unroll
    for (int r = 0; r < 4; r++) {
        l[r] = 0.f;
        oacc[r][0] = 0ull; oacc[r][1] = 0ull;
    }

    for (int j0 = 0; j0 < NJ; j0 += 32) {
        __syncthreads();   // prev-iter readers done; Q ready (iter 0)
#pragma unroll
        for (int p = 0; p < 2; p++) {
            const int idx = p * 256 + tid;
            const int r  = idx >> 4;
            const int c4 = (idx & 15) * 4;
            const float4 kv = *(const float4*)&g_k[(size_t)(j0 + r) * CS + h * DDIM + c4];
            Ks[(c4 + 0) * 36 + r] = kv.x;
            Ks[(c4 + 1) * 36 + r] = kv.y;
            Ks[(c4 + 2) * 36 + r] = kv.z;
            Ks[(c4 + 3) * 36 + r] = kv.w;
            const float4 vv = *(const float4*)&g_v[(size_t)(j0 + r) * CS + h * DDIM + c4];
            *(float4*)&Vs[r * 68 + c4] = vv;
        }
        __syncthreads();

        // S = Q K^T  (4 rows x 1 packed j-pair per thread, f32x2)
        ull s2p[4];
#pragma unroll
        for (int r = 0; r < 4; r++) s2p[r] = 0ull;
#pragma unroll 8
        for (int d = 0; d < 64; d++) {
            const float4 a4 = *(const float4*)&Qs[d * 68 + ty * 4];
            const ull bp = *(const ull*)&Ks[d * 36 + tx * 2];
            ffma2(s2p[0], f2dup(a4.x), bp);
            ffma2(s2p[1], f2dup(a4.y), bp);
            ffma2(s2p[2], f2dup(a4.z), bp);
            ffma2(s2p[3], f2dup(a4.w), bp);
        }

        // p = exp(s/8 + z); accumulate per-thread row sum
#pragma unroll
        for (int r = 0; r < 4; r++) {
            const float2 sv = f2unpack(s2p[r]);
            const float2 zv = *(const float2*)
                &g_z[((size_t)h * NI + (i0 + ty * 4 + r)) * NJ + j0 + tx * 2];
            const float p0 = __expf(fmaf(sv.x, 0.125f, zv.x));
            const float p1 = __expf(fmaf(sv.y, 0.125f, zv.y));
            l[r] += p0 + p1;
            *(float2*)&Ps[(ty * 4 + r) * 36 + tx * 2] = make_float2(p0, p1);
        }
        __syncthreads();

        // O += P @ V   (f32x2 along d)
#pragma unroll
        for (int jj4 = 0; jj4 < 32; jj4 += 4) {
            ull pd[4][4];
#pragma unroll
            for (int r = 0; r < 4; r++) {
                const float4 pv = *(const float4*)&Ps[(ty * 4 + r) * 36 + jj4];
                pd[r][0] = f2dup(pv.x); pd[r][1] = f2dup(pv.y);
                pd[r][2] = f2dup(pv.z); pd[r][3] = f2dup(pv.w);
            }
#pragma unroll
            for (int q = 0; q < 4; q++) {
                const ulonglong2 v2 = *(const ulonglong2*)&Vs[(jj4 + q) * 68 + tx * 4];
#pragma unroll
                for (int r = 0; r < 4; r++) {
                    ffma2(oacc[r][0], pd[r][q], v2.x);
                    ffma2(oacc[r][1], pd[r][q], v2.y);
                }
            }
        }
    }

#pragma unroll
    for (int r = 0; r < 4; r++) {
        float ls = l[r];
#pragma unroll
        for (int off = 8; off >= 1; off >>= 1)
            ls += __shfl_xor_sync(0xffffffffu, ls, off);
        const float inv = 1.f / ls;
        const float2 o0 = f2unpack(oacc[r][0]);
        const float2 o1 = f2unpack(oacc[r][1]);
        const size_t pos = (size_t)(i0 + ty * 4 + r) * CS + h * DDIM + tx * 4;
        const float4 gv = *(const float4*)&g_g[pos];     // fuse gate here
        float4 ov = make_float4(o0.x * inv * gv.x, o0.y * inv * gv.y,
                                o1.x * inv * gv.z, o1.y * inv * gv.w);
        *(float4*)&g_o[pos] = ov;
    }
}

// =====================================================================
// out = (g.*o) @ Wo^T   128x64x32 tiles, 8x2-ull microtile, f32x2
// =====================================================================
__global__ __launch_bounds__(256) void final_kernel(
    const float* __restrict__ Wo, float* __restrict__ out)
{
    __shared__ __align__(16) float As[32 * 132];
    __shared__ __align__(16) float Bs[32 * 68];
    const int SLA = 132, SLB = 68;
    const int tid = threadIdx.x;
    const int tx = tid & 15, ty = tid >> 4;
    const int row0 = blockIdx.y * 128, col0 = blockIdx.x * 64;

    ull acc[8][2];
#pragma unroll
    for (int i = 0; i < 8; i++) { acc[i][0] = 0ull; acc[i][1] = 0ull; }

    for (int kt = 0; kt < CS; kt += 32) {
#pragma unroll
        for (int p = 0; p < 4; p++) {
            const int idx = p * 256 + tid;     // 0..1023
            const int r   = idx >> 3;          // 0..127
            const int kc4 = (idx & 7) * 4;     // 0..28
            const float4 av = *(const float4*)&g_o[(size_t)(row0 + r) * CS + kt + kc4];
            As[(kc4 + 0) * SLA + r] = av.x;
            As[(kc4 + 1) * SLA + r] = av.y;
            As[(kc4 + 2) * SLA + r] = av.z;
            As[(kc4 + 3) * SLA + r] = av.w;
        }
#pragma unroll
        for (int p = 0; p < 2; p++) {
            const int idx = p * 256 + tid;     // 0..511
            const int r   = idx >> 3;          // 0..63
            const int kc4 = (idx & 7) * 4;
            const float4 bv = *(const float4*)&Wo[(size_t)(col0 + r) * CS + kt + kc4];
            Bs[(kc4 + 0) * SLB + r] = bv.x;
            Bs[(kc4 + 1) * SLB + r] = bv.y;
            Bs[(kc4 + 2) * SLB + r] = bv.z;
            Bs[(kc4 + 3) * SLB + r] = bv.w;
        }
        __syncthreads();
#pragma unroll 8
        for (int kk = 0; kk < 32; kk++) {
            const float4 a0 = *(const float4*)&As[kk * SLA + ty * 8];
            const float4 a1 = *(const float4*)&As[kk * SLA + ty * 8 + 4];
            const ulonglong2 b2 = *(const ulonglong2*)&Bs[kk * SLB + tx * 4];
            const ull aa[8] = {f2dup(a0.x), f2dup(a0.y), f2dup(a0.z), f2dup(a0.w),
                               f2dup(a1.x), f2dup(a1.y), f2dup(a1.z), f2dup(a1.w)};
#pragma unroll
            for (int i = 0; i < 8; i++) {
                ffma2(acc[i][0], aa[i], b2.x);
                ffma2(acc[i][1], aa[i], b2.y);
            }
        }
        __syncthreads();
    }

#pragma unroll
    for (int i = 0; i < 8; i++) {
        const int row = row0 + ty * 8 + i;
        const float2 c0 = f2unpack(acc[i][0]);
        const float2 c1 = f2unpack(acc[i][1]);
        float4 v = make_float4(c0.x, c0.y, c1.x, c1.y);
        *(float4*)&out[(size_t)row * CS + col0 + tx * 4] = v;
    }
}

// =====================================================================
extern "C" void kernel_launch(void* const* d_in, const int* in_sizes, int n_in,
                              void* d_out, int out_size)
{
    (void)in_sizes; (void)n_in; (void)out_size;
    const float* s    = (const float*)d_in[0];
    const float* kin  = (const float*)d_in[1];
    const float* mask = (const float*)d_in[2];
    const float* bias = (const float*)d_in[3];
    const float* Wq   = (const float*)d_in[4];
    const float* bq   = (const float*)d_in[5];
    const float* Wk   = (const float*)d_in[6];
    const float* Wv   = (const float*)d_in[7];
    const float* Wg   = (const float*)d_in[8];
    const float* Wo   = (const float*)d_in[9];
    const float* Wz   = (const float*)d_in[10];
    float* out = (float*)d_out;

    proj4_kernel<<<dim3(8, 8, 4), 256>>>(s, kin, Wq, bq, Wk, Wv, Wg);
    z_kernel<<<2 * NI, 256>>>(bias, Wz, mask);
    attn_kernel<<<dim3(NI / 64, HD), 256>>>();
    final_kernel<<<dim3(CS / 64, CS / 128), 256>>>(Wo, out);
}

// round 9
// speedup vs baseline: 1.3107x; 1.3023x over previous
#include <cuda_runtime.h>
#include <cuda_bf16.h>
#include <cstdint>

#define CS   1024
#define HD   16
#define DDIM 64
#define CZ   128
#define NI   1024
#define NJ   1024
#define BK   64

typedef unsigned long long ull;

// ---------------- scratch (device globals: allocation-free) ----------------
__device__ float g_q[NI * CS];                  // 4 MB
__device__ float g_k[NJ * CS];                  // 4 MB
__device__ float g_v[NJ * CS];                  // 4 MB
__device__ float g_g[NI * CS];                  // 4 MB
__device__ float g_z[(size_t)HD * NI * NJ];     // 64 MB

// bf16 hi/lo split matrices (2 MB each)
__device__ __nv_bfloat16 g_s_h[NI * CS],   g_s_l[NI * CS];
__device__ __nv_bfloat16 g_kin_h[NJ * CS], g_kin_l[NJ * CS];
__device__ __nv_bfloat16 g_wq_h[CS * CS],  g_wq_l[CS * CS];
__device__ __nv_bfloat16 g_wk_h[CS * CS],  g_wk_l[CS * CS];
__device__ __nv_bfloat16 g_wv_h[CS * CS],  g_wv_l[CS * CS];
__device__ __nv_bfloat16 g_wg_h[CS * CS],  g_wg_l[CS * CS];
__device__ __nv_bfloat16 g_wo_h[CS * CS],  g_wo_l[CS * CS];
__device__ __nv_bfloat16 g_go_h[NI * CS],  g_go_l[NI * CS];   // g .* o from attn

// ---------------- packed fp32x2 helpers (z / attn) ----------------
static __device__ __forceinline__ ull f2pack(float x, float y) {
    ull r; asm("mov.b64 %0, {%1, %2};" : "=l"(r) : "f"(x), "f"(y)); return r;
}
static __device__ __forceinline__ ull f2dup(float x) {
    ull r; asm("mov.b64 %0, {%1, %1};" : "=l"(r) : "f"(x)); return r;
}
static __device__ __forceinline__ void ffma2(ull& d, ull a, ull b) {
    asm("fma.rn.f32x2 %0, %1, %2, %0;" : "+l"(d) : "l"(a), "l"(b));
}
static __device__ __forceinline__ float2 f2unpack(ull v) {
    float2 r; asm("mov.b64 {%0, %1}, %2;" : "=f"(r.x), "=f"(r.y) : "l"(v)); return r;
}

// ---------------- mma.sync / ldmatrix helpers (baseline PTX, no 'a' feature) --
static __device__ __forceinline__ uint32_t smem_to_u32(const void* p) {
    uint32_t a;
    asm("{ .reg .u64 t; cvta.to.shared.u64 t, %1; cvt.u32.u64 %0, t; }" : "=r"(a) : "l"(p));
    return a;
}
static __device__ __forceinline__ void ldsm4(uint32_t* r, uint32_t addr) {
    asm volatile("ldmatrix.sync.aligned.m8n8.x4.shared.b16 {%0,%1,%2,%3}, [%4];"
                 : "=r"(r[0]), "=r"(r[1]), "=r"(r[2]), "=r"(r[3]) : "r"(addr));
}
static __device__ __forceinline__ void mma16816(float* c, const uint32_t* a, const uint32_t* b) {
    asm volatile("mma.sync.aligned.m16n8k16.row.col.f32.bf16.bf16.f32 "
                 "{%0,%1,%2,%3}, {%4,%5,%6,%7}, {%8,%9}, {%0,%1,%2,%3};"
                 : "+f"(c[0]), "+f"(c[1]), "+f"(c[2]), "+f"(c[3])
                 : "r"(a[0]), "r"(a[1]), "r"(a[2]), "r"(a[3]), "r"(b[0]), "r"(b[1]));
}

// =====================================================================
// fp32 -> bf16 hi/lo conversion (s, kin, Wq, Wk, Wv, Wg, Wo) one launch
// =====================================================================
static __device__ __forceinline__ void cvt_hilo(float v, __nv_bfloat16& h, __nv_bfloat16& l) {
    h = __float2bfloat16(v);
    l = __float2bfloat16(v - __bfloat162float(h));
}

__global__ __launch_bounds__(256) void conv_kernel(
    const float* __restrict__ s, const float* __restrict__ kin,
    const float* __restrict__ Wq, const float* __restrict__ Wk,
    const float* __restrict__ Wv, const float* __restrict__ Wg,
    const float* __restrict__ Wo)
{
    const int which = blockIdx.x >> 6;
    const int slice = blockIdx.x & 63;
    const float* src;
    __nv_bfloat16 *dh, *dl;
    switch (which) {
    case 0: src = s;   dh = g_s_h;   dl = g_s_l;   break;
    case 1: src = kin; dh = g_kin_h; dl = g_kin_l; break;
    case 2: src = Wq;  dh = g_wq_h;  dl = g_wq_l;  break;
    case 3: src = Wk;  dh = g_wk_h;  dl = g_wk_l;  break;
    case 4: src = Wv;  dh = g_wv_h;  dl = g_wv_l;  break;
    case 5: src = Wg;  dh = g_wg_h;  dl = g_wg_l;  break;
    default: src = Wo; dh = g_wo_h;  dl = g_wo_l;  break;
    }
    const int base = slice * 16384;
#pragma unroll 4
    for (int it = 0; it < 16; it++) {
        const int e = base + (it * 256 + threadIdx.x) * 4;
        const float4 v = *(const float4*)&src[e];
        __nv_bfloat16 h0, h1, h2, h3, l0, l1, l2, l3;
        cvt_hilo(v.x, h0, l0); cvt_hilo(v.y, h1, l1);
        cvt_hilo(v.z, h2, l2); cvt_hilo(v.w, h3, l3);
        *(__nv_bfloat162*)&dh[e]     = __halves2bfloat162(h0, h1);
        *(__nv_bfloat162*)&dh[e + 2] = __halves2bfloat162(h2, h3);
        *(__nv_bfloat162*)&dl[e]     = __halves2bfloat162(l0, l1);
        *(__nv_bfloat162*)&dl[e + 2] = __halves2bfloat162(l2, l3);
    }
}

// =====================================================================
// mma.sync bf16x3 GEMM: C[128x128 tile] = A @ B^T, fp32 out
// D += Ah·Bh + Ah·Bl + Al·Bh  (fp32 accumulate)
// BK=64, 8 warps x (32x64), single-stage 64KB smem, XOR-swizzled 16B chunks.
// MODE: 0 plain, 1 +biasv[col], 2 sigmoid
// =====================================================================
#define GEMM_SMEM 65536

template <int MODE>
static __device__ void gemm_mma_body(
    const __nv_bfloat16* __restrict__ Ahg, const __nv_bfloat16* __restrict__ Alg,
    const __nv_bfloat16* __restrict__ Bhg, const __nv_bfloat16* __restrict__ Blg,
    const float* __restrict__ biasv, float* __restrict__ C, char* dsm)
{
    const int tid  = threadIdx.x;
    const int warp = tid >> 5, lane = tid & 31;
    const int m0w  = (warp & 3) * 32;        // warp m-offset in tile
    const int n0w  = (warp >> 2) * 64;       // warp n-offset in tile
    const int rowA0 = blockIdx.y * 128;
    const int rowB0 = blockIdx.x * 128;
    const uint32_t sbase = smem_to_u32(dsm);
    // pieces: 0=Ah 1=Al 2=Bh 3=Bl, each 128 rows x 64 bf16 (=128B row, 8 chunks)
    const uint32_t soff[4] = {0u, 16384u, 32768u, 49152u};

    float acc[2][8][4];
#pragma unroll
    for (int mt = 0; mt < 2; mt++)
#pragma unroll
        for (int nt = 0; nt < 8; nt++)
#pragma unroll
            for (int q = 0; q < 4; q++) acc[mt][nt][q] = 0.f;

    // ldmatrix lane addressing
    const int a_row = lane & 15;             // row within 16-row tile
    const int a_kh  = lane >> 4;             // k-half chunk (0/1)
    const int b_row = ((lane >> 4) & 1) * 8 + (lane & 7);
    const int b_kh  = (lane >> 3) & 1;

    for (int c = 0; c < 16; c++) {
        const int kt = c * BK;
        const __nv_bfloat16* gsrc[4] = {Ahg, Alg, Bhg, Blg};
        const int grow[4] = {rowA0, rowA0, rowB0, rowB0};
#pragma unroll
        for (int piece = 0; piece < 4; piece++) {
#pragma unroll
            for (int p = 0; p < 4; p++) {
                const int idx = p * 256 + tid;      // 0..1023
                const int r = idx >> 3, ch = idx & 7;
                const uint4 v = *(const uint4*)
                    &gsrc[piece][(size_t)(grow[piece] + r) * CS + kt + ch * 8];
                *(uint4*)(dsm + soff[piece] + r * 128 + ((ch ^ (r & 7)) << 4)) = v;
            }
        }
        __syncthreads();

#pragma unroll
        for (int ks = 0; ks < 4; ks++) {
            uint32_t ah[2][4], al[2][4], bh[8][2], bl[8][2];
#pragma unroll
            for (int mt = 0; mt < 2; mt++) {
                const int r = m0w + mt * 16 + a_row;
                const int ch = ks * 2 + a_kh;
                const uint32_t off = r * 128 + ((ch ^ (r & 7)) << 4);
                ldsm4(ah[mt], sbase + soff[0] + off);
                ldsm4(al[mt], sbase + soff[1] + off);
            }
#pragma unroll
            for (int bq = 0; bq < 4; bq++) {
                const int r = n0w + bq * 16 + b_row;
                const int ch = ks * 2 + b_kh;
                const uint32_t off = r * 128 + ((ch ^ (r & 7)) << 4);
                uint32_t t[4];
                ldsm4(t, sbase + soff[2] + off);
                bh[2 * bq][0] = t[0]; bh[2 * bq][1] = t[1];
                bh[2 * bq + 1][0] = t[2]; bh[2 * bq + 1][1] = t[3];
                ldsm4(t, sbase + soff[3] + off);
                bl[2 * bq][0] = t[0]; bl[2 * bq][1] = t[1];
                bl[2 * bq + 1][0] = t[2]; bl[2 * bq + 1][1] = t[3];
            }
#pragma unroll
            for (int mt = 0; mt < 2; mt++)
#pragma unroll
                for (int nt = 0; nt < 8; nt++) {
                    mma16816(acc[mt][nt], ah[mt], bh[nt]);
                    mma16816(acc[mt][nt], ah[mt], bl[nt]);
                    mma16816(acc[mt][nt], al[mt], bh[nt]);
                }
        }
        __syncthreads();
    }

    // epilogue: c0,c1 = (row g, col 2tig, 2tig+1); c2,c3 = (row g+8, ...)
    const int g = lane >> 2, tig = lane & 3;
#pragma unroll
    for (int mt = 0; mt < 2; mt++)
#pragma unroll
        for (int nt = 0; nt < 8; nt++)
#pragma unroll
            for (int half = 0; half < 2; half++) {
                const int row = rowA0 + m0w + mt * 16 + g + half * 8;
                const int col = rowB0 + n0w + nt * 8 + tig * 2;
                float2 v = make_float2(acc[mt][nt][half * 2], acc[mt][nt][half * 2 + 1]);
                if (MODE == 1) {
                    v.x += biasv[col]; v.y += biasv[col + 1];
                } else if (MODE == 2) {
                    v.x = 1.f / (1.f + __expf(-v.x));
                    v.y = 1.f / (1.f + __expf(-v.y));
                }
                *(float2*)&C[(size_t)row * CS + col] = v;
            }
}

__global__ __launch_bounds__(256) void proj_mma_kernel(const float* __restrict__ bq)
{
    extern __shared__ char dsm[];
    switch (blockIdx.z) {
    case 0: gemm_mma_body<1>(g_s_h,   g_s_l,   g_wq_h, g_wq_l, bq,      g_q, dsm); break;
    case 1: gemm_mma_body<0>(g_kin_h, g_kin_l, g_wk_h, g_wk_l, nullptr, g_k, dsm); break;
    case 2: gemm_mma_body<0>(g_kin_h, g_kin_l, g_wv_h, g_wv_l, nullptr, g_v, dsm); break;
    default: gemm_mma_body<2>(g_s_h,  g_s_l,   g_wg_h, g_wg_l, nullptr, g_g, dsm); break;
    }
}

__global__ __launch_bounds__(256) void final_mma_kernel(float* __restrict__ out)
{
    extern __shared__ char dsm[];
    gemm_mma_body<0>(g_go_h, g_go_l, g_wo_h, g_wo_l, nullptr, out, dsm);
}

// =====================================================================
// z_kernel (measured R7 version): z[h,i,j] = bias[i,j,:]·Wz[:,h] + mask
// =====================================================================
__global__ __launch_bounds__(256) void z_kernel(
    const float* __restrict__ bias, const float* __restrict__ Wz,
    const float* __restrict__ mask)
{
    __shared__ ull Wzs[(HD / 2) * CZ];
    for (int t = threadIdx.x; t < (HD / 2) * CZ; t += 256) {
        const int hp = t >> 7, c = t & 127;
        Wzs[t] = f2pack(Wz[c * HD + hp * 2], Wz[c * HD + hp * 2 + 1]);
    }
    __syncthreads();

    const int idx = blockIdx.x;
    const int i   = idx >> 1;
    const int jb  = (idx & 1) * 512 + threadIdx.x;
    const float* base = bias + (size_t)i * NJ * CZ;

    ull acc2[2][HD / 2];
#pragma unroll
    for (int t = 0; t < 2; t++)
#pragma unroll
        for (int hp = 0; hp < HD / 2; hp++) acc2[t][hp] = 0ull;

    float4 bv[2];
#pragma unroll
    for (int t = 0; t < 2; t++)
        bv[t] = *(const float4*)&base[(size_t)(jb + t * 256) * CZ];

    for (int c4 = 0; c4 < CZ; c4 += 4) {
        float4 nv[2];
        if (c4 + 4 < CZ) {
#pragma unroll
            for (int t = 0; t < 2; t++)
                nv[t] = *(const float4*)&base[(size_t)(jb + t * 256) * CZ + c4 + 4];
        }
        {
            ull d0[2], d1[2];
#pragma unroll
            for (int t = 0; t < 2; t++) { d0[t] = f2dup(bv[t].x); d1[t] = f2dup(bv[t].y); }
#pragma unroll
            for (int hp = 0; hp < HD / 2; hp++) {
                const ulonglong2 w = *(const ulonglong2*)&Wzs[hp * CZ + c4];
#pragma unroll
                for (int t = 0; t < 2; t++) {
                    ffma2(acc2[t][hp], d0[t], w.x);
                    ffma2(acc2[t][hp], d1[t], w.y);
                }
            }
        }
        {
            ull d0[2], d1[2];
#pragma unroll
            for (int t = 0; t < 2; t++) { d0[t] = f2dup(bv[t].z); d1[t] = f2dup(bv[t].w); }
#pragma unroll
            for (int hp = 0; hp < HD / 2; hp++) {
                const ulonglong2 w = *(const ulonglong2*)&Wzs[hp * CZ + c4 + 2];
#pragma unroll
                for (int t = 0; t < 2; t++) {
                    ffma2(acc2[t][hp], d0[t], w.x);
                    ffma2(acc2[t][hp], d1[t], w.y);
                }
            }
        }
#pragma unroll
        for (int t = 0; t < 2; t++) bv[t] = nv[t];
    }

#pragma unroll
    for (int t = 0; t < 2; t++) {
        const int j = jb + t * 256;
        const float mterm = (1.0f - mask[j]) * (-1000000.0f);
#pragma unroll
        for (int hp = 0; hp < HD / 2; hp++) {
            const float2 zz = f2unpack(acc2[t][hp]);
            g_z[((size_t)(2 * hp + 0) * NI + i) * NJ + j] = zz.x + mterm;
            g_z[((size_t)(2 * hp + 1) * NI + i) * NJ + j] = zz.y + mterm;
        }
    }
}

// =====================================================================
// Attention (measured core); epilogue emits (g.*o) as bf16 hi/lo
// =====================================================================
__global__ __launch_bounds__(256) void attn_kernel()
{
    __shared__ __align__(16) float Qs[64 * 68];
    __shared__ __align__(16) float Ks[64 * 36];
    __shared__ __align__(16) float Vs[32 * 68];
    __shared__ __align__(16) float Ps[64 * 36];

    const int tid = threadIdx.x;
    const int tx = tid & 15, ty = tid >> 4;
    const int h  = blockIdx.y;
    const int i0 = blockIdx.x * 64;

#pragma unroll
    for (int p = 0; p < 4; p++) {
        const int idx = p * 256 + tid;
        const int r  = idx >> 4;
        const int c4 = (idx & 15) * 4;
        const float4 qv = *(const float4*)&g_q[(size_t)(i0 + r) * CS + h * DDIM + c4];
        Qs[(c4 + 0) * 68 + r] = qv.x;
        Qs[(c4 + 1) * 68 + r] = qv.y;
        Qs[(c4 + 2) * 68 + r] = qv.z;
        Qs[(c4 + 3) * 68 + r] = qv.w;
    }

    float l[4];
    ull oacc[4][2];
#pragma unroll
    for (int r = 0; r < 4; r++) {
        l[r] = 0.f;
        oacc[r][0] = 0ull; oacc[r][1] = 0ull;
    }

    for (int j0 = 0; j0 < NJ; j0 += 32) {
        __syncthreads();
#pragma unroll
        for (int p = 0; p < 2; p++) {
            const int idx = p * 256 + tid;
            const int r  = idx >> 4;
            const int c4 = (idx & 15) * 4;
            const float4 kv = *(const float4*)&g_k[(size_t)(j0 + r) * CS + h * DDIM + c4];
            Ks[(c4 + 0) * 36 + r] = kv.x;
            Ks[(c4 + 1) * 36 + r] = kv.y;
            Ks[(c4 + 2) * 36 + r] = kv.z;
            Ks[(c4 + 3) * 36 + r] = kv.w;
            const float4 vv = *(const float4*)&g_v[(size_t)(j0 + r) * CS + h * DDIM + c4];
            *(float4*)&Vs[r * 68 + c4] = vv;
        }
        __syncthreads();

        ull s2p[4];
#pragma unroll
        for (int r = 0; r < 4; r++) s2p[r] = 0ull;
#pragma unroll 8
        for (int d = 0; d < 64; d++) {
            const float4 a4 = *(const float4*)&Qs[d * 68 + ty * 4];
            const ull bp = *(const ull*)&Ks[d * 36 + tx * 2];
            ffma2(s2p[0], f2dup(a4.x), bp);
            ffma2(s2p[1], f2dup(a4.y), bp);
            ffma2(s2p[2], f2dup(a4.z), bp);
            ffma2(s2p[3], f2dup(a4.w), bp);
        }

#pragma unroll
        for (int r = 0; r < 4; r++) {
            const float2 sv = f2unpack(s2p[r]);
            const float2 zv = *(const float2*)
                &g_z[((size_t)h * NI + (i0 + ty * 4 + r)) * NJ + j0 + tx * 2];
            const float p0 = __expf(fmaf(sv.x, 0.125f, zv.x));
            const float p1 = __expf(fmaf(sv.y, 0.125f, zv.y));
            l[r] += p0 + p1;
            *(float2*)&Ps[(ty * 4 + r) * 36 + tx * 2] = make_float2(p0, p1);
        }
        __syncthreads();

#pragma unroll
        for (int jj4 = 0; jj4 < 32; jj4 += 4) {
            ull pd[4][4];
#pragma unroll
            for (int r = 0; r < 4; r++) {
                const float4 pv = *(const float4*)&Ps[(ty * 4 + r) * 36 + jj4];
                pd[r][0] = f2dup(pv.x); pd[r][1] = f2dup(pv.y);
                pd[r][2] = f2dup(pv.z); pd[r][3] = f2dup(pv.w);
            }
#pragma unroll
            for (int q = 0; q < 4; q++) {
                const ulonglong2 v2 = *(const ulonglong2*)&Vs[(jj4 + q) * 68 + tx * 4];
#pragma unroll
                for (int r = 0; r < 4; r++) {
                    ffma2(oacc[r][0], pd[r][q], v2.x);
                    ffma2(oacc[r][1], pd[r][q], v2.y);
                }
            }
        }
    }

#pragma unroll
    for (int r = 0; r < 4; r++) {
        float ls = l[r];
#pragma unroll
        for (int off = 8; off >= 1; off >>= 1)
            ls += __shfl_xor_sync(0xffffffffu, ls, off);
        const float inv = 1.f / ls;
        const float2 o0 = f2unpack(oacc[r][0]);
        const float2 o1 = f2unpack(oacc[r][1]);
        const size_t pos = (size_t)(i0 + ty * 4 + r) * CS + h * DDIM + tx * 4;
        const float4 gv = *(const float4*)&g_g[pos];
        const float4 ov = make_float4(o0.x * inv * gv.x, o0.y * inv * gv.y,
                                      o1.x * inv * gv.z, o1.y * inv * gv.w);
        __nv_bfloat16 h0, h1, h2, h3, l0, l1, l2, l3;
        cvt_hilo(ov.x, h0, l0); cvt_hilo(ov.y, h1, l1);
        cvt_hilo(ov.z, h2, l2); cvt_hilo(ov.w, h3, l3);
        *(__nv_bfloat162*)&g_go_h[pos]     = __halves2bfloat162(h0, h1);
        *(__nv_bfloat162*)&g_go_h[pos + 2] = __halves2bfloat162(h2, h3);
        *(__nv_bfloat162*)&g_go_l[pos]     = __halves2bfloat162(l0, l1);
        *(__nv_bfloat162*)&g_go_l[pos + 2] = __halves2bfloat162(l2, l3);
    }
}

// =====================================================================
extern "C" void kernel_launch(void* const* d_in, const int* in_sizes, int n_in,
                              void* d_out, int out_size)
{
    (void)in_sizes; (void)n_in; (void)out_size;
    const float* s    = (const float*)d_in[0];
    const float* kin  = (const float*)d_in[1];
    const float* mask = (const float*)d_in[2];
    const float* bias = (const float*)d_in[3];
    const float* Wq   = (const float*)d_in[4];
    const float* bq   = (const float*)d_in[5];
    const float* Wk   = (const float*)d_in[6];
    const float* Wv   = (const float*)d_in[7];
    const float* Wg   = (const float*)d_in[8];
    const float* Wo   = (const float*)d_in[9];
    const float* Wz   = (const float*)d_in[10];
    float* out = (float*)d_out;

    // host-side attribute sets (idempotent, not stream ops)
    cudaFuncSetAttribute(proj_mma_kernel,
                         cudaFuncAttributeMaxDynamicSharedMemorySize, GEMM_SMEM);
    cudaFuncSetAttribute(final_mma_kernel,
                         cudaFuncAttributeMaxDynamicSharedMemorySize, GEMM_SMEM);

    conv_kernel<<<7 * 64, 256>>>(s, kin, Wq, Wk, Wv, Wg, Wo);
    proj_mma_kernel<<<dim3(8, 8, 4), 256, GEMM_SMEM>>>(bq);
    z_kernel<<<2 * NI, 256>>>(bias, Wz, mask);
    attn_kernel<<<dim3(NI / 64, HD), 256>>>();
    final_mma_kernel<<<dim3(8, 8), 256, GEMM_SMEM>>>(out);
}

// round 10
// speedup vs baseline: 1.5963x; 1.2179x over previous
#include <cuda_runtime.h>
#include <cuda_bf16.h>
#include <cstdint>

#define CS   1024
#define HD   16
#define DDIM 64
#define CZ   128
#define NI   1024
#define NJ   1024
#define BK   64

typedef unsigned long long ull;

// ---------------- scratch (device globals: allocation-free) ----------------
__device__ float g_g[NI * CS];                  // 4 MB (gate, fp32)
__device__ float g_z[(size_t)HD * NI * NJ];     // 64 MB

// bf16 hi/lo split matrices (2 MB each)
__device__ __nv_bfloat16 g_s_h[NI * CS],   g_s_l[NI * CS];
__device__ __nv_bfloat16 g_kin_h[NJ * CS], g_kin_l[NJ * CS];
__device__ __nv_bfloat16 g_wq_h[CS * CS],  g_wq_l[CS * CS];
__device__ __nv_bfloat16 g_wk_h[CS * CS],  g_wk_l[CS * CS];
__device__ __nv_bfloat16 g_wv_h[CS * CS],  g_wv_l[CS * CS];
__device__ __nv_bfloat16 g_wg_h[CS * CS],  g_wg_l[CS * CS];
__device__ __nv_bfloat16 g_wo_h[CS * CS],  g_wo_l[CS * CS];
__device__ __nv_bfloat16 g_qh[NI * CS],  g_ql[NI * CS];      // q/8 (bias folded)
__device__ __nv_bfloat16 g_kh[NJ * CS],  g_kl[NJ * CS];
__device__ __nv_bfloat16 g_vh[NJ * CS],  g_vl[NJ * CS];
__device__ __nv_bfloat16 g_go_h[NI * CS], g_go_l[NI * CS];   // g .* o from attn

// ---------------- packed fp32x2 helpers (z kernel) ----------------
static __device__ __forceinline__ ull f2pack(float x, float y) {
    ull r; asm("mov.b64 %0, {%1, %2};" : "=l"(r) : "f"(x), "f"(y)); return r;
}
static __device__ __forceinline__ ull f2dup(float x) {
    ull r; asm("mov.b64 %0, {%1, %1};" : "=l"(r) : "f"(x)); return r;
}
static __device__ __forceinline__ void ffma2(ull& d, ull a, ull b) {
    asm("fma.rn.f32x2 %0, %1, %2, %0;" : "+l"(d) : "l"(a), "l"(b));
}
static __device__ __forceinline__ float2 f2unpack(ull v) {
    float2 r; asm("mov.b64 {%0, %1}, %2;" : "=f"(r.x), "=f"(r.y) : "l"(v)); return r;
}

// ---------------- mma.sync / ldmatrix helpers (baseline PTX) ----------------
static __device__ __forceinline__ uint32_t smem_to_u32(const void* p) {
    uint32_t a;
    asm("{ .reg .u64 t; cvta.to.shared.u64 t, %1; cvt.u32.u64 %0, t; }" : "=r"(a) : "l"(p));
    return a;
}
static __device__ __forceinline__ void ldsm4(uint32_t* r, uint32_t addr) {
    asm volatile("ldmatrix.sync.aligned.m8n8.x4.shared.b16 {%0,%1,%2,%3}, [%4];"
                 : "=r"(r[0]), "=r"(r[1]), "=r"(r[2]), "=r"(r[3]) : "r"(addr));
}
static __device__ __forceinline__ void ldsm4_t(uint32_t* r, uint32_t addr) {
    asm volatile("ldmatrix.sync.aligned.m8n8.x4.trans.shared.b16 {%0,%1,%2,%3}, [%4];"
                 : "=r"(r[0]), "=r"(r[1]), "=r"(r[2]), "=r"(r[3]) : "r"(addr));
}
static __device__ __forceinline__ void mma16816(float* c, const uint32_t* a, const uint32_t* b) {
    asm volatile("mma.sync.aligned.m16n8k16.row.col.f32.bf16.bf16.f32 "
                 "{%0,%1,%2,%3}, {%4,%5,%6,%7}, {%8,%9}, {%0,%1,%2,%3};"
                 : "+f"(c[0]), "+f"(c[1]), "+f"(c[2]), "+f"(c[3])
                 : "r"(a[0]), "r"(a[1]), "r"(a[2]), "r"(a[3]), "r"(b[0]), "r"(b[1]));
}

static __device__ __forceinline__ void cvt_hilo(float v, __nv_bfloat16& h, __nv_bfloat16& l) {
    h = __float2bfloat16(v);
    l = __float2bfloat16(v - __bfloat162float(h));
}

// =====================================================================
// fp32 -> bf16 hi/lo conversion (s, kin, Wq, Wk, Wv, Wg, Wo)
// =====================================================================
__global__ __launch_bounds__(256) void conv_kernel(
    const float* __restrict__ s, const float* __restrict__ kin,
    const float* __restrict__ Wq, const float* __restrict__ Wk,
    const float* __restrict__ Wv, const float* __restrict__ Wg,
    const float* __restrict__ Wo)
{
    const int which = blockIdx.x >> 6;
    const int slice = blockIdx.x & 63;
    const float* src;
    __nv_bfloat16 *dh, *dl;
    switch (which) {
    case 0: src = s;   dh = g_s_h;   dl = g_s_l;   break;
    case 1: src = kin; dh = g_kin_h; dl = g_kin_l; break;
    case 2: src = Wq;  dh = g_wq_h;  dl = g_wq_l;  break;
    case 3: src = Wk;  dh = g_wk_h;  dl = g_wk_l;  break;
    case 4: src = Wv;  dh = g_wv_h;  dl = g_wv_l;  break;
    case 5: src = Wg;  dh = g_wg_h;  dl = g_wg_l;  break;
    default: src = Wo; dh = g_wo_h;  dl = g_wo_l;  break;
    }
    const int base = slice * 16384;
#pragma unroll 4
    for (int it = 0; it < 16; it++) {
        const int e = base + (it * 256 + threadIdx.x) * 4;
        const float4 v = *(const float4*)&src[e];
        __nv_bfloat16 h0, h1, h2, h3, l0, l1, l2, l3;
        cvt_hilo(v.x, h0, l0); cvt_hilo(v.y, h1, l1);
        cvt_hilo(v.z, h2, l2); cvt_hilo(v.w, h3, l3);
        *(__nv_bfloat162*)&dh[e]     = __halves2bfloat162(h0, h1);
        *(__nv_bfloat162*)&dh[e + 2] = __halves2bfloat162(h2, h3);
        *(__nv_bfloat162*)&dl[e]     = __halves2bfloat162(l0, l1);
        *(__nv_bfloat162*)&dl[e + 2] = __halves2bfloat162(l2, l3);
    }
}

// =====================================================================
// mma.sync bf16x3 GEMM: C[128x128 tile] = A @ B^T
// OUT: 0 fp32 plain, 1 (acc+bias)*0.125 -> bf16 hi/lo (q),
//      2 sigmoid -> fp32 (g), 3 plain -> bf16 hi/lo (k, v)
// =====================================================================
#define GEMM_SMEM 65536

template <int OUT>
static __device__ void gemm_mma_body(
    const __nv_bfloat16* __restrict__ Ahg, const __nv_bfloat16* __restrict__ Alg,
    const __nv_bfloat16* __restrict__ Bhg, const __nv_bfloat16* __restrict__ Blg,
    const float* __restrict__ biasv, float* __restrict__ Cf,
    __nv_bfloat16* __restrict__ Ch, __nv_bfloat16* __restrict__ Cl, char* dsm)
{
    const int tid  = threadIdx.x;
    const int warp = tid >> 5, lane = tid & 31;
    const int m0w  = (warp & 3) * 32;
    const int n0w  = (warp >> 2) * 64;
    const int rowA0 = blockIdx.y * 128;
    const int rowB0 = blockIdx.x * 128;
    const uint32_t sbase = smem_to_u32(dsm);
    const uint32_t soff[4] = {0u, 16384u, 32768u, 49152u};

    float acc[2][8][4];
#pragma unroll
    for (int mt = 0; mt < 2; mt++)
#pragma unroll
        for (int nt = 0; nt < 8; nt++)
#pragma unroll
            for (int q = 0; q < 4; q++) acc[mt][nt][q] = 0.f;

    const int a_row = lane & 15;
    const int a_kh  = lane >> 4;
    const int b_row = ((lane >> 4) & 1) * 8 + (lane & 7);
    const int b_kh  = (lane >> 3) & 1;

    for (int c = 0; c < 16; c++) {
        const int kt = c * BK;
        const __nv_bfloat16* gsrc[4] = {Ahg, Alg, Bhg, Blg};
        const int grow[4] = {rowA0, rowA0, rowB0, rowB0};
#pragma unroll
        for (int piece = 0; piece < 4; piece++) {
#pragma unroll
            for (int p = 0; p < 4; p++) {
                const int idx = p * 256 + tid;
                const int r = idx >> 3, ch = idx & 7;
                const uint4 v = *(const uint4*)
                    &gsrc[piece][(size_t)(grow[piece] + r) * CS + kt + ch * 8];
                *(uint4*)(dsm + soff[piece] + r * 128 + ((ch ^ (r & 7)) << 4)) = v;
            }
        }
        __syncthreads();

#pragma unroll
        for (int ks = 0; ks < 4; ks++) {
            uint32_t ah[2][4], al[2][4], bh[8][2], bl[8][2];
#pragma unroll
            for (int mt = 0; mt < 2; mt++) {
                const int r = m0w + mt * 16 + a_row;
                const int ch = ks * 2 + a_kh;
                const uint32_t off = r * 128 + ((ch ^ (r & 7)) << 4);
                ldsm4(ah[mt], sbase + soff[0] + off);
                ldsm4(al[mt], sbase + soff[1] + off);
            }
#pragma unroll
            for (int bq2 = 0; bq2 < 4; bq2++) {
                const int r = n0w + bq2 * 16 + b_row;
                const int ch = ks * 2 + b_kh;
                const uint32_t off = r * 128 + ((ch ^ (r & 7)) << 4);
                uint32_t t[4];
                ldsm4(t, sbase + soff[2] + off);
                bh[2 * bq2][0] = t[0]; bh[2 * bq2][1] = t[1];
                bh[2 * bq2 + 1][0] = t[2]; bh[2 * bq2 + 1][1] = t[3];
                ldsm4(t, sbase + soff[3] + off);
                bl[2 * bq2][0] = t[0]; bl[2 * bq2][1] = t[1];
                bl[2 * bq2 + 1][0] = t[2]; bl[2 * bq2 + 1][1] = t[3];
            }
#pragma unroll
            for (int mt = 0; mt < 2; mt++)
#pragma unroll
                for (int nt = 0; nt < 8; nt++) {
                    mma16816(acc[mt][nt], ah[mt], bh[nt]);
                    mma16816(acc[mt][nt], ah[mt], bl[nt]);
                    mma16816(acc[mt][nt], al[mt], bh[nt]);
                }
        }
        __syncthreads();
    }

    const int g2 = lane >> 2, tig = lane & 3;
#pragma unroll
    for (int mt = 0; mt < 2; mt++)
#pragma unroll
        for (int nt = 0; nt < 8; nt++)
#pragma unroll
            for (int half = 0; half < 2; half++) {
                const int row = rowA0 + m0w + mt * 16 + g2 + half * 8;
                const int col = rowB0 + n0w + nt * 8 + tig * 2;
                float2 v = make_float2(acc[mt][nt][half * 2], acc[mt][nt][half * 2 + 1]);
                if (OUT == 1) {
                    v.x = (v.x + biasv[col]) * 0.125f;
                    v.y = (v.y + biasv[col + 1]) * 0.125f;
                } else if (OUT == 2) {
                    v.x = 1.f / (1.f + __expf(-v.x));
                    v.y = 1.f / (1.f + __expf(-v.y));
                }
                if (OUT == 0 || OUT == 2) {
                    *(float2*)&Cf[(size_t)row * CS + col] = v;
                } else {
                    __nv_bfloat16 h0, h1, l0, l1;
                    cvt_hilo(v.x, h0, l0); cvt_hilo(v.y, h1, l1);
                    *(__nv_bfloat162*)&Ch[(size_t)row * CS + col] = __halves2bfloat162(h0, h1);
                    *(__nv_bfloat162*)&Cl[(size_t)row * CS + col] = __halves2bfloat162(l0, l1);
                }
            }
}

__global__ __launch_bounds__(256) void proj_mma_kernel(const float* __restrict__ bq)
{
    extern __shared__ char dsm[];
    switch (blockIdx.z) {
    case 0: gemm_mma_body<1>(g_s_h,   g_s_l,   g_wq_h, g_wq_l, bq,      nullptr, g_qh, g_ql, dsm); break;
    case 1: gemm_mma_body<3>(g_kin_h, g_kin_l, g_wk_h, g_wk_l, nullptr, nullptr, g_kh, g_kl, dsm); break;
    case 2: gemm_mma_body<3>(g_kin_h, g_kin_l, g_wv_h, g_wv_l, nullptr, nullptr, g_vh, g_vl, dsm); break;
    default: gemm_mma_body<2>(g_s_h,  g_s_l,   g_wg_h, g_wg_l, nullptr, g_g,     nullptr, nullptr, dsm); break;
    }
}

__global__ __launch_bounds__(256) void final_mma_kernel(float* __restrict__ out)
{
    extern __shared__ char dsm[];
    gemm_mma_body<0>(g_go_h, g_go_l, g_wo_h, g_wo_l, nullptr, out, nullptr, nullptr, dsm);
}

// =====================================================================
// z_kernel (measured): z[h,i,j] = bias[i,j,:]·Wz[:,h] + (1-mask[j])*(-1e6)
// =====================================================================
__global__ __launch_bounds__(256) void z_kernel(
    const float* __restrict__ bias, const float* __restrict__ Wz,
    const float* __restrict__ mask)
{
    __shared__ ull Wzs[(HD / 2) * CZ];
    for (int t = threadIdx.x; t < (HD / 2) * CZ; t += 256) {
        const int hp = t >> 7, c = t & 127;
        Wzs[t] = f2pack(Wz[c * HD + hp * 2], Wz[c * HD + hp * 2 + 1]);
    }
    __syncthreads();

    const int idx = blockIdx.x;
    const int i   = idx >> 1;
    const int jb  = (idx & 1) * 512 + threadIdx.x;
    const float* base = bias + (size_t)i * NJ * CZ;

    ull acc2[2][HD / 2];
#pragma unroll
    for (int t = 0; t < 2; t++)
#pragma unroll
        for (int hp = 0; hp < HD / 2; hp++) acc2[t][hp] = 0ull;

    float4 bv[2];
#pragma unroll
    for (int t = 0; t < 2; t++)
        bv[t] = *(const float4*)&base[(size_t)(jb + t * 256) * CZ];

    for (int c4 = 0; c4 < CZ; c4 += 4) {
        float4 nv[2];
        if (c4 + 4 < CZ) {
#pragma unroll
            for (int t = 0; t < 2; t++)
                nv[t] = *(const float4*)&base[(size_t)(jb + t * 256) * CZ + c4 + 4];
        }
        {
            ull d0[2], d1[2];
#pragma unroll
            for (int t = 0; t < 2; t++) { d0[t] = f2dup(bv[t].x); d1[t] = f2dup(bv[t].y); }
#pragma unroll
            for (int hp = 0; hp < HD / 2; hp++) {
                const ulonglong2 w = *(const ulonglong2*)&Wzs[hp * CZ + c4];
#pragma unroll
                for (int t = 0; t < 2; t++) {
                    ffma2(acc2[t][hp], d0[t], w.x);
                    ffma2(acc2[t][hp], d1[t], w.y);
                }
            }
        }
        {
            ull d0[2], d1[2];
#pragma unroll
            for (int t = 0; t < 2; t++) { d0[t] = f2dup(bv[t].z); d1[t] = f2dup(bv[t].w); }
#pragma unroll
            for (int hp = 0; hp < HD / 2; hp++) {
                const ulonglong2 w = *(const ulonglong2*)&Wzs[hp * CZ + c4 + 2];
#pragma unroll
                for (int t = 0; t < 2; t++) {
                    ffma2(acc2[t][hp], d0[t], w.x);
                    ffma2(acc2[t][hp], d1[t], w.y);
                }
            }
        }
#pragma unroll
        for (int t = 0; t < 2; t++) bv[t] = nv[t];
    }

#pragma unroll
    for (int t = 0; t < 2; t++) {
        const int j = jb + t * 256;
        const float mterm = (1.0f - mask[j]) * (-1000000.0f);
#pragma unroll
        for (int hp = 0; hp < HD / 2; hp++) {
            const float2 zz = f2unpack(acc2[t][hp]);
            g_z[((size_t)(2 * hp + 0) * NI + i) * NJ + j] = zz.x + mterm;
            g_z[((size_t)(2 * hp + 1) * NI + i) * NJ + j] = zz.y + mterm;
        }
    }
}

// =====================================================================
// Attention via mma.sync: block = (64 i-rows, head), BJ=64, 8 warps.
// S = Q K^T (bf16x3), p = exp(S + z) (q pre-scaled), P bf16 hi/lo in smem,
// O += P V (bf16x3, V^T via ldmatrix.trans). Gate g fused in epilogue.
// smem: Qh Ql Kh Kl Vh Vl Ph Pl (8x 8KB) + l_red 512B = 66048 B
// =====================================================================
#define ATTN_SMEM 66048

__global__ __launch_bounds__(256) void attn_kernel()
{
    extern __shared__ char dsm[];
    const uint32_t sb = smem_to_u32(dsm);
    const int tid  = threadIdx.x;
    const int warp = tid >> 5, lane = tid & 31;
    const int mt   = warp >> 1;      // 0..3  (16-row m-tile)
    const int nh   = warp & 1;       // 0..1  (32-col n-half)
    const int g2   = lane >> 2, tig = lane & 3;
    const int h  = blockIdx.y;
    const int i0 = blockIdx.x * 64;

    const uint32_t Qh = 0, Ql = 8192, Kh = 16384, Kl = 24576,
                   Vh = 32768, Vl = 40960, Ph = 49152, Pl = 57344, LR = 65536;

    const int a_row = lane & 15;
    const int a_kh  = lane >> 4;
    const int b_row = ((lane >> 4) & 1) * 8 + (lane & 7);
    const int b_kh  = (lane >> 3) & 1;
    const int t_row = lane & 15;          // trans-B: k-row within 16
    const int t_n8  = (lane >> 4) * 8;    // trans-B: +8 col group

    // load Q tile hi/lo (rows i0.., cols h*64..)
    {
        const __nv_bfloat16* srcs[2] = {g_qh, g_ql};
        const uint32_t dsts[2] = {Qh, Ql};
#pragma unroll
        for (int piece = 0; piece < 2; piece++)
#pragma unroll
            for (int p = 0; p < 2; p++) {
                const int idx = p * 256 + tid;
                const int r = idx >> 3, ch = idx & 7;
                const uint4 v = *(const uint4*)&srcs[piece][(size_t)(i0 + r) * CS + h * DDIM + ch * 8];
                *(uint4*)(dsm + dsts[piece] + r * 128 + ((ch ^ (r & 7)) << 4)) = v;
            }
    }

    float acc_o[4][4];
    float l[2] = {0.f, 0.f};
#pragma unroll
    for (int nt = 0; nt < 4; nt++)
#pragma unroll
        for (int q = 0; q < 4; q++) acc_o[nt][q] = 0.f;

    for (int j0 = 0; j0 < NJ; j0 += 64) {
        __syncthreads();
        {
            const __nv_bfloat16* srcs[4] = {g_kh, g_kl, g_vh, g_vl};
            const uint32_t dsts[4] = {Kh, Kl, Vh, Vl};
#pragma unroll
            for (int piece = 0; piece < 4; piece++)
#pragma unroll
                for (int p = 0; p < 2; p++) {
                    const int idx = p * 256 + tid;
                    const int r = idx >> 3, ch = idx & 7;
                    const uint4 v = *(const uint4*)&srcs[piece][(size_t)(j0 + r) * CS + h * DDIM + ch * 8];
                    *(uint4*)(dsm + dsts[piece] + r * 128 + ((ch ^ (r & 7)) << 4)) = v;
                }
        }
        __syncthreads();

        // ---- S = Q K^T  (warp: m16 x n32) ----
        float acc_s[4][4];
#pragma unroll
        for (int nt = 0; nt < 4; nt++)
#pragma unroll
            for (int q = 0; q < 4; q++) acc_s[nt][q] = 0.f;

#pragma unroll
        for (int ks = 0; ks < 4; ks++) {
            uint32_t ah[4], al[4];
            {
                const int r = mt * 16 + a_row;
                const int ch = ks * 2 + a_kh;
                const uint32_t off = r * 128 + ((ch ^ (r & 7)) << 4);
                ldsm4(ah, sb + Qh + off);
                ldsm4(al, sb + Ql + off);
            }
            uint32_t bh[4][2], bl[4][2];
#pragma unroll
            for (int bq2 = 0; bq2 < 2; bq2++) {
                const int r = nh * 32 + bq2 * 16 + b_row;
                const int ch = ks * 2 + b_kh;
                const uint32_t off = r * 128 + ((ch ^ (r & 7)) << 4);
                uint32_t t[4];
                ldsm4(t, sb + Kh + off);
                bh[2 * bq2][0] = t[0]; bh[2 * bq2][1] = t[1];
                bh[2 * bq2 + 1][0] = t[2]; bh[2 * bq2 + 1][1] = t[3];
                ldsm4(t, sb + Kl + off);
                bl[2 * bq2][0] = t[0]; bl[2 * bq2][1] = t[1];
                bl[2 * bq2 + 1][0] = t[2]; bl[2 * bq2 + 1][1] = t[3];
            }
#pragma unroll
            for (int nt = 0; nt < 4; nt++) {
                mma16816(acc_s[nt], ah, bh[nt]);
                mma16816(acc_s[nt], ah, bl[nt]);
                mma16816(acc_s[nt], al, bh[nt]);
            }
        }

        // ---- softmax numerator: p = exp(S + z); write P hi/lo to smem ----
#pragma unroll
        for (int nt = 0; nt < 4; nt++)
#pragma unroll
            for (int half = 0; half < 2; half++) {
                const int rl = mt * 16 + g2 + half * 8;
                const int cl = nh * 32 + nt * 8 + tig * 2;
                const float2 zv = *(const float2*)
                    &g_z[((size_t)h * NI + (i0 + rl)) * NJ + j0 + cl];
                const float p0 = __expf(acc_s[nt][half * 2]     + zv.x);
                const float p1 = __expf(acc_s[nt][half * 2 + 1] + zv.y);
                l[half] += p0 + p1;
                __nv_bfloat16 h0, h1, l0, l1;
                cvt_hilo(p0, h0, l0); cvt_hilo(p1, h1, l1);
                const uint32_t byte = cl * 2;
                const uint32_t off = rl * 128 + ((((byte >> 4) ^ (rl & 7))) << 4) + (byte & 15);
                *(__nv_bfloat162*)(dsm + Ph + off) = __halves2bfloat162(h0, h1);
                *(__nv_bfloat162*)(dsm + Pl + off) = __halves2bfloat162(l0, l1);
            }
        __syncthreads();

        // ---- O += P V  (warp: m16 rows x n32 d-cols; B = V^T via ldsm.trans) ----
#pragma unroll
        for (int ks = 0; ks < 4; ks++) {
            uint32_t ph_[4], pl_[4];
            {
                const int r = mt * 16 + a_row;
                const int ch = ks * 2 + a_kh;
                const uint32_t off = r * 128 + ((ch ^ (r & 7)) << 4);
                ldsm4(ph_, sb + Ph + off);
                ldsm4(pl_, sb + Pl + off);
            }
            uint32_t vh_[4][2], vl_[4][2];
#pragma unroll
            for (int bq2 = 0; bq2 < 2; bq2++) {
                const int r = ks * 16 + t_row;
                const int n0 = nh * 32 + bq2 * 16 + t_n8;
                const int ch = n0 >> 3;
                const uint32_t off = r * 128 + ((ch ^ (r & 7)) << 4);
                uint32_t t[4];
                ldsm4_t(t, sb + Vh + off);
                vh_[2 * bq2][0] = t[0]; vh_[2 * bq2][1] = t[1];
                vh_[2 * bq2 + 1][0] = t[2]; vh_[2 * bq2 + 1][1] = t[3];
                ldsm4_t(t, sb + Vl + off);
                vl_[2 * bq2][0] = t[0]; vl_[2 * bq2][1] = t[1];
                vl_[2 * bq2 + 1][0] = t[2]; vl_[2 * bq2 + 1][1] = t[3];
            }
#pragma unroll
            for (int nt = 0; nt < 4; nt++) {
                mma16816(acc_o[nt], ph_, vh_[nt]);
                mma16816(acc_o[nt], pl_, vh_[nt]);
                mma16816(acc_o[nt], ph_, vl_[nt]);
            }
        }
    }

    // ---- l reduction: over tig quad, then across warp-halves via smem ----
#pragma unroll
    for (int half = 0; half < 2; half++) {
        l[half] += __shfl_xor_sync(0xffffffffu, l[half], 1);
        l[half] += __shfl_xor_sync(0xffffffffu, l[half], 2);
    }
    if (tig == 0) {
        ((float*)(dsm + LR))[(mt * 16 + g2) * 2 + nh]     = l[0];
        ((float*)(dsm + LR))[(mt * 16 + g2 + 8) * 2 + nh] = l[1];
    }
    __syncthreads();

#pragma unroll
    for (int half = 0; half < 2; half++) {
        const int rl = mt * 16 + g2 + half * 8;
        const float lt = ((float*)(dsm + LR))[rl * 2] + ((float*)(dsm + LR))[rl * 2 + 1];
        const float inv = 1.f / lt;
        const int row = i0 + rl;
#pragma unroll
        for (int nt = 0; nt < 4; nt++) {
            const int dcol = h * DDIM + nh * 32 + nt * 8 + tig * 2;
            const size_t pos = (size_t)row * CS + dcol;
            const float2 gv = *(const float2*)&g_g[pos];
            const float o0 = acc_o[nt][half * 2]     * inv * gv.x;
            const float o1 = acc_o[nt][half * 2 + 1] * inv * gv.y;
            __nv_bfloat16 h0, h1, l0, l1;
            cvt_hilo(o0, h0, l0); cvt_hilo(o1, h1, l1);
            *(__nv_bfloat162*)&g_go_h[pos] = __halves2bfloat162(h0, h1);
            *(__nv_bfloat162*)&g_go_l[pos] = __halves2bfloat162(l0, l1);
        }
    }
}

// =====================================================================
extern "C" void kernel_launch(void* const* d_in, const int* in_sizes, int n_in,
                              void* d_out, int out_size)
{
    (void)in_sizes; (void)n_in; (void)out_size;
    const float* s    = (const float*)d_in[0];
    const float* kin  = (const float*)d_in[1];
    const float* mask = (const float*)d_in[2];
    const float* bias = (const float*)d_in[3];
    const float* Wq   = (const float*)d_in[4];
    const float* bq   = (const float*)d_in[5];
    const float* Wk   = (const float*)d_in[6];
    const float* Wv   = (const float*)d_in[7];
    const float* Wg   = (const float*)d_in[8];
    const float* Wo   = (const float*)d_in[9];
    const float* Wz   = (const float*)d_in[10];
    float* out = (float*)d_out;

    // host-side attribute sets (idempotent, not stream ops)
    cudaFuncSetAttribute(proj_mma_kernel,
                         cudaFuncAttributeMaxDynamicSharedMemorySize, GEMM_SMEM);
    cudaFuncSetAttribute(final_mma_kernel,
                         cudaFuncAttributeMaxDynamicSharedMemorySize, GEMM_SMEM);
    cudaFuncSetAttribute(attn_kernel,
                         cudaFuncAttributeMaxDynamicSharedMemorySize, ATTN_SMEM);

    conv_kernel<<<7 * 64, 256>>>(s, kin, Wq, Wk, Wv, Wg, Wo);
    proj_mma_kernel<<<dim3(8, 8, 4), 256, GEMM_SMEM>>>(bq);
    z_kernel<<<2 * NI, 256>>>(bias, Wz, mask);
    attn_kernel<<<dim3(NI / 64, HD), 256, ATTN_SMEM>>>();
    final_mma_kernel<<<dim3(8, 8), 256, GEMM_SMEM>>>(out);
}